// round 7
// baseline (speedup 1.0000x reference)
#include <cuda_runtime.h>
#include <math.h>

#define T_TOK 1024
#define HDIM  2048
#define NEXP  16
#define KSEL  4
#define IDIM  1408
#define ISDIM 2816

typedef unsigned long long u64;

// packed fp32x2 FMA: acc.lo += a.lo*b.lo ; acc.hi += a.hi*b.hi (exact fp32 lanewise)
#define FMA2(acc, a, b) asm("fma.rn.f32x2 %0, %1, %2, %0;" : "+l"(acc) : "l"(a), "l"(b))

__device__ __forceinline__ u64 bcast(float x) {
    u64 r; asm("mov.b64 %0, {%1, %1};" : "=l"(r) : "f"(x)); return r;
}
__device__ __forceinline__ float lo32(u64 v) { return __uint_as_float((unsigned)v); }
__device__ __forceinline__ float hi32(u64 v) { return __uint_as_float((unsigned)(v >> 32)); }

// ---------------- scratch ----------------
__device__ int   g_counts[NEXP];
__device__ int   g_tokens[NEXP * T_TOK];
__device__ float g_wts[NEXP * T_TOK];
__device__ float g_act[(size_t)NEXP * T_TOK * IDIM];
__device__ float g_acts[(size_t)T_TOK * ISDIM];

__global__ void zero_counts_kernel() {
    if (threadIdx.x < NEXP) g_counts[threadIdx.x] = 0;
}

// ---------------- router ----------------
__global__ void gate_kernel(const float* __restrict__ x, const float* __restrict__ gw) {
    int t = blockIdx.x;
    __shared__ float xs[HDIM];
    __shared__ float logits[NEXP];
    const float* xrow = x + (size_t)t * HDIM;
    for (int i = threadIdx.x; i < HDIM; i += blockDim.x) xs[i] = xrow[i];
    __syncthreads();

    int warp = threadIdx.x >> 5, lane = threadIdx.x & 31;
    for (int e = warp; e < NEXP; e += 8) {
        const float* grow = gw + (size_t)e * HDIM;
        float s = 0.f;
        for (int h = lane; h < HDIM; h += 32) s += xs[h] * grow[h];
        #pragma unroll
        for (int o = 16; o > 0; o >>= 1) s += __shfl_xor_sync(0xffffffffu, s, o);
        if (lane == 0) logits[e] = s;
    }
    __syncthreads();

    if (threadIdx.x == 0) {
        float mx = -1e30f;
        for (int e = 0; e < NEXP; e++) mx = fmaxf(mx, logits[e]);
        float sc[NEXP]; float se = 0.f;
        for (int e = 0; e < NEXP; e++) { sc[e] = expf(logits[e] - mx); se += sc[e]; }
        float inv = 1.f / se;
        for (int e = 0; e < NEXP; e++) sc[e] *= inv;

        int idx[KSEL]; float w[KSEL]; float wsum = 0.f;
        bool used[NEXP];
        for (int e = 0; e < NEXP; e++) used[e] = false;
        for (int k = 0; k < KSEL; k++) {
            int best = 0; float bv = -1.f;
            for (int e = 0; e < NEXP; e++)
                if (!used[e] && sc[e] > bv) { bv = sc[e]; best = e; }
            used[best] = true; idx[k] = best; w[k] = bv; wsum += bv;
        }
        float iw = 1.f / wsum;
        for (int k = 0; k < KSEL; k++) {
            int e = idx[k];
            int pos = atomicAdd(&g_counts[e], 1);
            g_tokens[e * T_TOK + pos] = t;
            g_wts[e * T_TOK + pos]    = w[k] * iw;
        }
    }
}

// ---------------- gate/up GEMM + SwiGLU (f32x2, register-broadcast B) ----------------
// C-tile 128x64, both g and u. acc packed along M row pairs.
__global__ __launch_bounds__(256, 2)
void up_gemm_kernel(const float* __restrict__ X,
                    const float* __restrict__ Wg, const float* __restrict__ Wu,
                    long wExpStride, int ldB, int routed)
{
    int e = blockIdx.z;
    int count = routed ? g_counts[e] : T_TOK;
    int m0 = blockIdx.y * 128;
    if (m0 >= count) return;
    int n0 = blockIdx.x * 64;
    const int Kdim = HDIM;

    const float* Bg = Wg + (size_t)e * wExpStride + n0;
    const float* Bu = Wu + (size_t)e * wExpStride + n0;
    const int* toks = routed ? (g_tokens + e * T_TOK) : nullptr;

    __shared__ __align__(16) float As[16][128];   // col-major A slab
    __shared__ __align__(16) float Sg[16][64];
    __shared__ __align__(16) float Su[16][64];

    int tid = threadIdx.x;
    int tx = tid & 15, ty = tid >> 4;

    int arow0 = tid >> 2;
    int arow1 = arow0 + 64;
    int ac4   = (tid & 3) * 4;
    bool v0 = (m0 + arow0) < count;
    bool v1 = (m0 + arow1) < count;
    int tok0 = v0 ? (routed ? toks[m0 + arow0] : (m0 + arow0)) : 0;
    int tok1 = v1 ? (routed ? toks[m0 + arow1] : (m0 + arow1)) : 0;
    const float* xp0 = X + (size_t)tok0 * Kdim + ac4;
    const float* xp1 = X + (size_t)tok1 * Kdim + ac4;

    int brow = tid >> 4;
    int bc4  = (tid & 15) * 4;
    const float* bgp = Bg + (size_t)brow * ldB + bc4;
    const float* bup = Bu + (size_t)brow * ldB + bc4;

    u64 accg[4][4], accu[4][4];
    #pragma unroll
    for (int i = 0; i < 4; i++)
        #pragma unroll
        for (int j = 0; j < 4; j++) { accg[i][j] = 0ull; accu[i][j] = 0ull; }

    float4 ra0 = v0 ? *(const float4*)(xp0) : make_float4(0.f, 0.f, 0.f, 0.f);
    float4 ra1 = v1 ? *(const float4*)(xp1) : make_float4(0.f, 0.f, 0.f, 0.f);
    float4 rbg = *(const float4*)(bgp);
    float4 rbu = *(const float4*)(bup);

    for (int k0 = 0; k0 < Kdim; k0 += 16) {
        __syncthreads();
        As[ac4 + 0][arow0] = ra0.x; As[ac4 + 1][arow0] = ra0.y;
        As[ac4 + 2][arow0] = ra0.z; As[ac4 + 3][arow0] = ra0.w;
        As[ac4 + 0][arow1] = ra1.x; As[ac4 + 1][arow1] = ra1.y;
        As[ac4 + 2][arow1] = ra1.z; As[ac4 + 3][arow1] = ra1.w;
        *(float4*)&Sg[brow][bc4] = rbg;
        *(float4*)&Su[brow][bc4] = rbu;
        __syncthreads();

        int kn = k0 + 16;
        if (kn < Kdim) {
            ra0 = v0 ? *(const float4*)(xp0 + kn) : make_float4(0.f, 0.f, 0.f, 0.f);
            ra1 = v1 ? *(const float4*)(xp1 + kn) : make_float4(0.f, 0.f, 0.f, 0.f);
            rbg = *(const float4*)(bgp + (size_t)kn * ldB);
            rbu = *(const float4*)(bup + (size_t)kn * ldB);
        }

        #pragma unroll
        for (int kk = 0; kk < 16; kk++) {
            ulonglong2 aA = *(const ulonglong2*)&As[kk][ty * 8];
            ulonglong2 aB = *(const ulonglong2*)&As[kk][ty * 8 + 4];
            u64 a[4] = { aA.x, aA.y, aB.x, aB.y };
            float4 bg4 = *(const float4*)&Sg[kk][tx * 4];
            float4 bu4 = *(const float4*)&Su[kk][tx * 4];
            u64 bg[4] = { bcast(bg4.x), bcast(bg4.y), bcast(bg4.z), bcast(bg4.w) };
            u64 bu[4] = { bcast(bu4.x), bcast(bu4.y), bcast(bu4.z), bcast(bu4.w) };
            #pragma unroll
            for (int i = 0; i < 4; i++)
                #pragma unroll
                for (int j = 0; j < 4; j++) {
                    FMA2(accg[i][j], a[i], bg[j]);
                    FMA2(accu[i][j], a[i], bu[j]);
                }
        }
    }

    float* actBase = routed ? (g_act + (size_t)e * T_TOK * IDIM) : g_acts;
    int actLd = routed ? IDIM : ISDIM;
    #pragma unroll
    for (int ip = 0; ip < 4; ip++) {
        #pragma unroll
        for (int half = 0; half < 2; half++) {
            int m = m0 + ty * 8 + ip * 2 + half;
            if (m >= count) continue;
            float w = routed ? g_wts[e * T_TOK + m] : 1.0f;
            float vals[4];
            #pragma unroll
            for (int j = 0; j < 4; j++) {
                float g = half ? hi32(accg[ip][j]) : lo32(accg[ip][j]);
                float u = half ? hi32(accu[ip][j]) : lo32(accu[ip][j]);
                float s = g / (1.f + expf(-g));
                vals[j] = s * u * w;
            }
            *(float4*)&actBase[(size_t)m * actLd + n0 + tx * 4] = *(float4*)vals;
        }
    }
}

// ---------------- down-proj GEMM (f32x2, 128x128 tile) ----------------
// Per-thread: 4 row-pairs x 8 cols; cols split {tx*4, 64+tx*4} for conflict-free LDS.
__global__ __launch_bounds__(256, 2)
void down_gemm_kernel(const float* __restrict__ Wd, long wExpStride,
                      float* __restrict__ out, int routed)
{
    int e = blockIdx.z;
    int count = routed ? g_counts[e] : T_TOK;
    int m0 = blockIdx.y * 128;
    if (m0 >= count) return;
    int n0 = blockIdx.x * 128;
    int Kdim = routed ? IDIM : ISDIM;

    const float* A = routed ? (g_act + (size_t)e * T_TOK * IDIM) : g_acts;
    int lda = Kdim;
    const float* B = Wd + (size_t)e * wExpStride + n0;   // row stride HDIM

    __shared__ __align__(16) float As[16][128];
    __shared__ __align__(16) float Bs[16][128];

    int tid = threadIdx.x;
    int tx = tid & 15, ty = tid >> 4;

    int arow0 = tid >> 2;
    int arow1 = arow0 + 64;
    int ac4   = (tid & 3) * 4;
    bool v0 = (m0 + arow0) < count;
    bool v1 = (m0 + arow1) < count;
    const float* ap0 = A + (size_t)(m0 + arow0) * lda + ac4;
    const float* ap1 = A + (size_t)(m0 + arow1) * lda + ac4;

    int brow = tid >> 4;
    int bc8  = (tid & 15) * 8;
    const float* bp = B + (size_t)brow * HDIM + bc8;

    u64 acc[4][8];
    #pragma unroll
    for (int i = 0; i < 4; i++)
        #pragma unroll
        for (int j = 0; j < 8; j++) acc[i][j] = 0ull;

    float4 ra0 = v0 ? *(const float4*)(ap0) : make_float4(0.f, 0.f, 0.f, 0.f);
    float4 ra1 = v1 ? *(const float4*)(ap1) : make_float4(0.f, 0.f, 0.f, 0.f);
    float4 rb0 = *(const float4*)(bp);
    float4 rb1 = *(const float4*)(bp + 4);

    for (int k0 = 0; k0 < Kdim; k0 += 16) {
        __syncthreads();
        As[ac4 + 0][arow0] = ra0.x; As[ac4 + 1][arow0] = ra0.y;
        As[ac4 + 2][arow0] = ra0.z; As[ac4 + 3][arow0] = ra0.w;
        As[ac4 + 0][arow1] = ra1.x; As[ac4 + 1][arow1] = ra1.y;
        As[ac4 + 2][arow1] = ra1.z; As[ac4 + 3][arow1] = ra1.w;
        *(float4*)&Bs[brow][bc8]     = rb0;
        *(float4*)&Bs[brow][bc8 + 4] = rb1;
        __syncthreads();

        int kn = k0 + 16;
        if (kn < Kdim) {
            ra0 = v0 ? *(const float4*)(ap0 + kn) : make_float4(0.f, 0.f, 0.f, 0.f);
            ra1 = v1 ? *(const float4*)(ap1 + kn) : make_float4(0.f, 0.f, 0.f, 0.f);
            rb0 = *(const float4*)(bp + (size_t)kn * HDIM);
            rb1 = *(const float4*)(bp + (size_t)kn * HDIM + 4);
        }

        #pragma unroll
        for (int kk = 0; kk < 16; kk++) {
            ulonglong2 aA = *(const ulonglong2*)&As[kk][ty * 8];
            ulonglong2 aB = *(const ulonglong2*)&As[kk][ty * 8 + 4];
            u64 a[4] = { aA.x, aA.y, aB.x, aB.y };
            float4 b0 = *(const float4*)&Bs[kk][tx * 4];        // cols tx*4..+3
            float4 b1 = *(const float4*)&Bs[kk][64 + tx * 4];   // cols 64+tx*4..+3
            u64 b[8] = { bcast(b0.x), bcast(b0.y), bcast(b0.z), bcast(b0.w),
                         bcast(b1.x), bcast(b1.y), bcast(b1.z), bcast(b1.w) };
            #pragma unroll
            for (int i = 0; i < 4; i++)
                #pragma unroll
                for (int j = 0; j < 8; j++)
                    FMA2(acc[i][j], a[i], b[j]);
        }
    }

    const int* toks = routed ? (g_tokens + e * T_TOK) : nullptr;
    #pragma unroll
    for (int ip = 0; ip < 4; ip++) {
        #pragma unroll
        for (int half = 0; half < 2; half++) {
            int m = m0 + ty * 8 + ip * 2 + half;
            if (m >= count) continue;
            float vals0[4], vals1[4];
            #pragma unroll
            for (int j = 0; j < 4; j++) {
                vals0[j] = half ? hi32(acc[ip][j])     : lo32(acc[ip][j]);
                vals1[j] = half ? hi32(acc[ip][j + 4]) : lo32(acc[ip][j + 4]);
            }
            if (routed) {
                int t = toks[m];
                float* op = out + (size_t)t * HDIM + n0;
                #pragma unroll
                for (int j = 0; j < 4; j++) {
                    atomicAdd(op + tx * 4 + j,      vals0[j]);
                    atomicAdd(op + 64 + tx * 4 + j, vals1[j]);
                }
            } else {
                float* op = out + (size_t)m * HDIM + n0;
                *(float4*)(op + tx * 4)      = *(float4*)vals0;
                *(float4*)(op + 64 + tx * 4) = *(float4*)vals1;
            }
        }
    }
}

// ---------------- launch ----------------
extern "C" void kernel_launch(void* const* d_in, const int* in_sizes, int n_in,
                              void* d_out, int out_size) {
    (void)in_sizes; (void)n_in; (void)out_size;
    const float* x       = (const float*)d_in[0];
    const float* gate_w  = (const float*)d_in[1];
    const float* w_gate  = (const float*)d_in[2];
    const float* w_up    = (const float*)d_in[3];
    const float* w_down  = (const float*)d_in[4];
    const float* sw_gate = (const float*)d_in[5];
    const float* sw_up   = (const float*)d_in[6];
    const float* sw_down = (const float*)d_in[7];
    float* out = (float*)d_out;

    zero_counts_kernel<<<1, 32>>>();
    gate_kernel<<<T_TOK, 256>>>(x, gate_w);

    dim3 g1r(IDIM / 64, T_TOK / 128, NEXP);
    up_gemm_kernel<<<g1r, 256>>>(x, w_gate, w_up, (long)HDIM * IDIM, IDIM, 1);

    dim3 g1s(ISDIM / 64, T_TOK / 128, 1);
    up_gemm_kernel<<<g1s, 256>>>(x, sw_gate, sw_up, 0L, ISDIM, 0);

    dim3 g2s(HDIM / 128, T_TOK / 128, 1);
    down_gemm_kernel<<<g2s, 256>>>(sw_down, 0L, out, 0);

    dim3 g2r(HDIM / 128, T_TOK / 128, NEXP);
    down_gemm_kernel<<<g2r, 256>>>(w_down, (long)IDIM * HDIM, out, 1);
}

// round 11
// speedup vs baseline: 1.0022x; 1.0022x over previous
#include <cuda_runtime.h>
#include <math.h>

#define T_TOK 1024
#define HDIM  2048
#define NEXP  16
#define KSEL  4
#define IDIM  1408
#define ISDIM 2816

typedef unsigned long long u64;

// packed fp32x2 FMA: acc.lo += a.lo*b.lo ; acc.hi += a.hi*b.hi (exact fp32 lanewise)
#define FMA2(acc, a, b) asm("fma.rn.f32x2 %0, %1, %2, %0;" : "+l"(acc) : "l"(a), "l"(b))

__device__ __forceinline__ u64 bcast(float x) {
    u64 r; asm("mov.b64 %0, {%1, %1};" : "=l"(r) : "f"(x)); return r;
}
__device__ __forceinline__ float lo32(u64 v) { return __uint_as_float((unsigned)v); }
__device__ __forceinline__ float hi32(u64 v) { return __uint_as_float((unsigned)(v >> 32)); }

// ---------------- scratch ----------------
__device__ int   g_counts[NEXP];
__device__ int   g_tokens[NEXP * T_TOK];
__device__ float g_wts[NEXP * T_TOK];
__device__ float g_act[(size_t)NEXP * T_TOK * IDIM];
__device__ float g_acts[(size_t)T_TOK * ISDIM];

__global__ void zero_counts_kernel() {
    if (threadIdx.x < NEXP) g_counts[threadIdx.x] = 0;
}

// ---------------- router ----------------
__global__ void gate_kernel(const float* __restrict__ x, const float* __restrict__ gw) {
    int t = blockIdx.x;
    __shared__ float xs[HDIM];
    __shared__ float logits[NEXP];
    const float* xrow = x + (size_t)t * HDIM;
    for (int i = threadIdx.x; i < HDIM; i += blockDim.x) xs[i] = xrow[i];
    __syncthreads();

    int warp = threadIdx.x >> 5, lane = threadIdx.x & 31;
    for (int e = warp; e < NEXP; e += 8) {
        const float* grow = gw + (size_t)e * HDIM;
        float s = 0.f;
        for (int h = lane; h < HDIM; h += 32) s += xs[h] * grow[h];
        #pragma unroll
        for (int o = 16; o > 0; o >>= 1) s += __shfl_xor_sync(0xffffffffu, s, o);
        if (lane == 0) logits[e] = s;
    }
    __syncthreads();

    if (threadIdx.x == 0) {
        float mx = -1e30f;
        for (int e = 0; e < NEXP; e++) mx = fmaxf(mx, logits[e]);
        float sc[NEXP]; float se = 0.f;
        for (int e = 0; e < NEXP; e++) { sc[e] = expf(logits[e] - mx); se += sc[e]; }
        float inv = 1.f / se;
        for (int e = 0; e < NEXP; e++) sc[e] *= inv;

        int idx[KSEL]; float w[KSEL]; float wsum = 0.f;
        bool used[NEXP];
        for (int e = 0; e < NEXP; e++) used[e] = false;
        for (int k = 0; k < KSEL; k++) {
            int best = 0; float bv = -1.f;
            for (int e = 0; e < NEXP; e++)
                if (!used[e] && sc[e] > bv) { bv = sc[e]; best = e; }
            used[best] = true; idx[k] = best; w[k] = bv; wsum += bv;
        }
        float iw = 1.f / wsum;
        for (int k = 0; k < KSEL; k++) {
            int e = idx[k];
            int pos = atomicAdd(&g_counts[e], 1);
            g_tokens[e * T_TOK + pos] = t;
            g_wts[e * T_TOK + pos]    = w[k] * iw;
        }
    }
}

// ---------------- gate/up GEMM + SwiGLU (f32x2, register-broadcast B) ----------------
// C-tile 128x64, both g and u. acc packed along M row pairs.
__global__ __launch_bounds__(256, 2)
void up_gemm_kernel(const float* __restrict__ X,
                    const float* __restrict__ Wg, const float* __restrict__ Wu,
                    long wExpStride, int ldB, int routed)
{
    int e = blockIdx.z;
    int count = routed ? g_counts[e] : T_TOK;
    int m0 = blockIdx.y * 128;
    if (m0 >= count) return;
    int n0 = blockIdx.x * 64;
    const int Kdim = HDIM;

    const float* Bg = Wg + (size_t)e * wExpStride + n0;
    const float* Bu = Wu + (size_t)e * wExpStride + n0;
    const int* toks = routed ? (g_tokens + e * T_TOK) : nullptr;

    __shared__ __align__(16) float As[16][128];   // col-major A slab
    __shared__ __align__(16) float Sg[16][64];
    __shared__ __align__(16) float Su[16][64];

    int tid = threadIdx.x;
    int tx = tid & 15, ty = tid >> 4;

    int arow0 = tid >> 2;
    int arow1 = arow0 + 64;
    int ac4   = (tid & 3) * 4;
    bool v0 = (m0 + arow0) < count;
    bool v1 = (m0 + arow1) < count;
    int tok0 = v0 ? (routed ? toks[m0 + arow0] : (m0 + arow0)) : 0;
    int tok1 = v1 ? (routed ? toks[m0 + arow1] : (m0 + arow1)) : 0;
    const float* xp0 = X + (size_t)tok0 * Kdim + ac4;
    const float* xp1 = X + (size_t)tok1 * Kdim + ac4;

    int brow = tid >> 4;
    int bc4  = (tid & 15) * 4;
    const float* bgp = Bg + (size_t)brow * ldB + bc4;
    const float* bup = Bu + (size_t)brow * ldB + bc4;

    u64 accg[4][4], accu[4][4];
    #pragma unroll
    for (int i = 0; i < 4; i++)
        #pragma unroll
        for (int j = 0; j < 4; j++) { accg[i][j] = 0ull; accu[i][j] = 0ull; }

    float4 ra0 = v0 ? *(const float4*)(xp0) : make_float4(0.f, 0.f, 0.f, 0.f);
    float4 ra1 = v1 ? *(const float4*)(xp1) : make_float4(0.f, 0.f, 0.f, 0.f);
    float4 rbg = *(const float4*)(bgp);
    float4 rbu = *(const float4*)(bup);

    for (int k0 = 0; k0 < Kdim; k0 += 16) {
        __syncthreads();
        As[ac4 + 0][arow0] = ra0.x; As[ac4 + 1][arow0] = ra0.y;
        As[ac4 + 2][arow0] = ra0.z; As[ac4 + 3][arow0] = ra0.w;
        As[ac4 + 0][arow1] = ra1.x; As[ac4 + 1][arow1] = ra1.y;
        As[ac4 + 2][arow1] = ra1.z; As[ac4 + 3][arow1] = ra1.w;
        *(float4*)&Sg[brow][bc4] = rbg;
        *(float4*)&Su[brow][bc4] = rbu;
        __syncthreads();

        int kn = k0 + 16;
        if (kn < Kdim) {
            ra0 = v0 ? *(const float4*)(xp0 + kn) : make_float4(0.f, 0.f, 0.f, 0.f);
            ra1 = v1 ? *(const float4*)(xp1 + kn) : make_float4(0.f, 0.f, 0.f, 0.f);
            rbg = *(const float4*)(bgp + (size_t)kn * ldB);
            rbu = *(const float4*)(bup + (size_t)kn * ldB);
        }

        #pragma unroll
        for (int kk = 0; kk < 16; kk++) {
            ulonglong2 aA = *(const ulonglong2*)&As[kk][ty * 8];
            ulonglong2 aB = *(const ulonglong2*)&As[kk][ty * 8 + 4];
            u64 a[4] = { aA.x, aA.y, aB.x, aB.y };
            float4 bg4 = *(const float4*)&Sg[kk][tx * 4];
            float4 bu4 = *(const float4*)&Su[kk][tx * 4];
            u64 bg[4] = { bcast(bg4.x), bcast(bg4.y), bcast(bg4.z), bcast(bg4.w) };
            u64 bu[4] = { bcast(bu4.x), bcast(bu4.y), bcast(bu4.z), bcast(bu4.w) };
            #pragma unroll
            for (int i = 0; i < 4; i++)
                #pragma unroll
                for (int j = 0; j < 4; j++) {
                    FMA2(accg[i][j], a[i], bg[j]);
                    FMA2(accu[i][j], a[i], bu[j]);
                }
        }
    }

    float* actBase = routed ? (g_act + (size_t)e * T_TOK * IDIM) : g_acts;
    int actLd = routed ? IDIM : ISDIM;
    #pragma unroll
    for (int ip = 0; ip < 4; ip++) {
        #pragma unroll
        for (int half = 0; half < 2; half++) {
            int m = m0 + ty * 8 + ip * 2 + half;
            if (m >= count) continue;
            float w = routed ? g_wts[e * T_TOK + m] : 1.0f;
            float vals[4];
            #pragma unroll
            for (int j = 0; j < 4; j++) {
                float g = half ? hi32(accg[ip][j]) : lo32(accg[ip][j]);
                float u = half ? hi32(accu[ip][j]) : lo32(accu[ip][j]);
                float s = g / (1.f + expf(-g));
                vals[j] = s * u * w;
            }
            *(float4*)&actBase[(size_t)m * actLd + n0 + tx * 4] = *(float4*)vals;
        }
    }
}

// ---------------- down-proj GEMM (f32x2, 128x128 tile) ----------------
// Per-thread: 4 row-pairs x 8 cols; cols split {tx*4, 64+tx*4} for conflict-free LDS.
__global__ __launch_bounds__(256, 2)
void down_gemm_kernel(const float* __restrict__ Wd, long wExpStride,
                      float* __restrict__ out, int routed)
{
    int e = blockIdx.z;
    int count = routed ? g_counts[e] : T_TOK;
    int m0 = blockIdx.y * 128;
    if (m0 >= count) return;
    int n0 = blockIdx.x * 128;
    int Kdim = routed ? IDIM : ISDIM;

    const float* A = routed ? (g_act + (size_t)e * T_TOK * IDIM) : g_acts;
    int lda = Kdim;
    const float* B = Wd + (size_t)e * wExpStride + n0;   // row stride HDIM

    __shared__ __align__(16) float As[16][128];
    __shared__ __align__(16) float Bs[16][128];

    int tid = threadIdx.x;
    int tx = tid & 15, ty = tid >> 4;

    int arow0 = tid >> 2;
    int arow1 = arow0 + 64;
    int ac4   = (tid & 3) * 4;
    bool v0 = (m0 + arow0) < count;
    bool v1 = (m0 + arow1) < count;
    const float* ap0 = A + (size_t)(m0 + arow0) * lda + ac4;
    const float* ap1 = A + (size_t)(m0 + arow1) * lda + ac4;

    int brow = tid >> 4;
    int bc8  = (tid & 15) * 8;
    const float* bp = B + (size_t)brow * HDIM + bc8;

    u64 acc[4][8];
    #pragma unroll
    for (int i = 0; i < 4; i++)
        #pragma unroll
        for (int j = 0; j < 8; j++) acc[i][j] = 0ull;

    float4 ra0 = v0 ? *(const float4*)(ap0) : make_float4(0.f, 0.f, 0.f, 0.f);
    float4 ra1 = v1 ? *(const float4*)(ap1) : make_float4(0.f, 0.f, 0.f, 0.f);
    float4 rb0 = *(const float4*)(bp);
    float4 rb1 = *(const float4*)(bp + 4);

    for (int k0 = 0; k0 < Kdim; k0 += 16) {
        __syncthreads();
        As[ac4 + 0][arow0] = ra0.x; As[ac4 + 1][arow0] = ra0.y;
        As[ac4 + 2][arow0] = ra0.z; As[ac4 + 3][arow0] = ra0.w;
        As[ac4 + 0][arow1] = ra1.x; As[ac4 + 1][arow1] = ra1.y;
        As[ac4 + 2][arow1] = ra1.z; As[ac4 + 3][arow1] = ra1.w;
        *(float4*)&Bs[brow][bc8]     = rb0;
        *(float4*)&Bs[brow][bc8 + 4] = rb1;
        __syncthreads();

        int kn = k0 + 16;
        if (kn < Kdim) {
            ra0 = v0 ? *(const float4*)(ap0 + kn) : make_float4(0.f, 0.f, 0.f, 0.f);
            ra1 = v1 ? *(const float4*)(ap1 + kn) : make_float4(0.f, 0.f, 0.f, 0.f);
            rb0 = *(const float4*)(bp + (size_t)kn * HDIM);
            rb1 = *(const float4*)(bp + (size_t)kn * HDIM + 4);
        }

        #pragma unroll
        for (int kk = 0; kk < 16; kk++) {
            ulonglong2 aA = *(const ulonglong2*)&As[kk][ty * 8];
            ulonglong2 aB = *(const ulonglong2*)&As[kk][ty * 8 + 4];
            u64 a[4] = { aA.x, aA.y, aB.x, aB.y };
            float4 b0 = *(const float4*)&Bs[kk][tx * 4];        // cols tx*4..+3
            float4 b1 = *(const float4*)&Bs[kk][64 + tx * 4];   // cols 64+tx*4..+3
            u64 b[8] = { bcast(b0.x), bcast(b0.y), bcast(b0.z), bcast(b0.w),
                         bcast(b1.x), bcast(b1.y), bcast(b1.z), bcast(b1.w) };
            #pragma unroll
            for (int i = 0; i < 4; i++)
                #pragma unroll
                for (int j = 0; j < 8; j++)
                    FMA2(acc[i][j], a[i], b[j]);
        }
    }

    const int* toks = routed ? (g_tokens + e * T_TOK) : nullptr;
    #pragma unroll
    for (int ip = 0; ip < 4; ip++) {
        #pragma unroll
        for (int half = 0; half < 2; half++) {
            int m = m0 + ty * 8 + ip * 2 + half;
            if (m >= count) continue;
            float vals0[4], vals1[4];
            #pragma unroll
            for (int j = 0; j < 4; j++) {
                vals0[j] = half ? hi32(acc[ip][j])     : lo32(acc[ip][j]);
                vals1[j] = half ? hi32(acc[ip][j + 4]) : lo32(acc[ip][j + 4]);
            }
            if (routed) {
                int t = toks[m];
                float* op = out + (size_t)t * HDIM + n0;
                #pragma unroll
                for (int j = 0; j < 4; j++) {
                    atomicAdd(op + tx * 4 + j,      vals0[j]);
                    atomicAdd(op + 64 + tx * 4 + j, vals1[j]);
                }
            } else {
                float* op = out + (size_t)m * HDIM + n0;
                *(float4*)(op + tx * 4)      = *(float4*)vals0;
                *(float4*)(op + 64 + tx * 4) = *(float4*)vals1;
            }
        }
    }
}

// ---------------- launch ----------------
extern "C" void kernel_launch(void* const* d_in, const int* in_sizes, int n_in,
                              void* d_out, int out_size) {
    (void)in_sizes; (void)n_in; (void)out_size;
    const float* x       = (const float*)d_in[0];
    const float* gate_w  = (const float*)d_in[1];
    const float* w_gate  = (const float*)d_in[2];
    const float* w_up    = (const float*)d_in[3];
    const float* w_down  = (const float*)d_in[4];
    const float* sw_gate = (const float*)d_in[5];
    const float* sw_up   = (const float*)d_in[6];
    const float* sw_down = (const float*)d_in[7];
    float* out = (float*)d_out;

    zero_counts_kernel<<<1, 32>>>();
    gate_kernel<<<T_TOK, 256>>>(x, gate_w);

    dim3 g1r(IDIM / 64, T_TOK / 128, NEXP);
    up_gemm_kernel<<<g1r, 256>>>(x, w_gate, w_up, (long)HDIM * IDIM, IDIM, 1);

    dim3 g1s(ISDIM / 64, T_TOK / 128, 1);
    up_gemm_kernel<<<g1s, 256>>>(x, sw_gate, sw_up, 0L, ISDIM, 0);

    dim3 g2s(HDIM / 128, T_TOK / 128, 1);
    down_gemm_kernel<<<g2s, 256>>>(sw_down, 0L, out, 0);

    dim3 g2r(HDIM / 128, T_TOK / 128, NEXP);
    down_gemm_kernel<<<g2r, 256>>>(w_down, (long)IDIM * HDIM, out, 1);
}

// round 16
// speedup vs baseline: 1.5340x; 1.5307x over previous
#include <cuda_runtime.h>
#include <cuda_bf16.h>
#include <stdint.h>
#include <math.h>

#define T_TOK 1024
#define HDIM  2048
#define NEXP  16
#define KSEL  4
#define IDIM  1408
#define ISDIM 2816
#define AST   40          // smem row stride in bf16 elements (80 bytes)

// ================= scratch =================
__device__ int   g_counts[NEXP];
__device__ int   g_tokens[NEXP * T_TOK];
__device__ float g_wts[NEXP * T_TOK];

__device__ __nv_bfloat16 g_xh[T_TOK * HDIM], g_xl[T_TOK * HDIM];
__device__ __nv_bfloat16 g_wgh[(size_t)NEXP * IDIM * HDIM], g_wgl[(size_t)NEXP * IDIM * HDIM];
__device__ __nv_bfloat16 g_wuh[(size_t)NEXP * IDIM * HDIM], g_wul[(size_t)NEXP * IDIM * HDIM];
__device__ __nv_bfloat16 g_wdh[(size_t)NEXP * HDIM * IDIM], g_wdl[(size_t)NEXP * HDIM * IDIM];
__device__ __nv_bfloat16 g_sgh[(size_t)ISDIM * HDIM], g_sgl[(size_t)ISDIM * HDIM];
__device__ __nv_bfloat16 g_suh[(size_t)ISDIM * HDIM], g_sul[(size_t)ISDIM * HDIM];
__device__ __nv_bfloat16 g_sdh[(size_t)HDIM * ISDIM], g_sdl[(size_t)HDIM * ISDIM];
__device__ __nv_bfloat16 g_ah[(size_t)NEXP * T_TOK * IDIM], g_al[(size_t)NEXP * T_TOK * IDIM];
__device__ __nv_bfloat16 g_sah[(size_t)T_TOK * ISDIM], g_sal[(size_t)T_TOK * ISDIM];

// ================= helpers =================
__device__ __forceinline__ void split_bf16(float v, __nv_bfloat16& h, __nv_bfloat16& l) {
    h = __float2bfloat16_rn(v);
    l = __float2bfloat16_rn(v - __bfloat162float(h));
}

__device__ __forceinline__ void mma16816(float* c, const unsigned* a, const unsigned* b) {
    asm volatile(
        "mma.sync.aligned.m16n8k16.row.col.f32.bf16.bf16.f32 "
        "{%0,%1,%2,%3}, {%4,%5,%6,%7}, {%8,%9}, {%0,%1,%2,%3};"
        : "+f"(c[0]), "+f"(c[1]), "+f"(c[2]), "+f"(c[3])
        : "r"(a[0]), "r"(a[1]), "r"(a[2]), "r"(a[3]), "r"(b[0]), "r"(b[1]));
}

__device__ __forceinline__ unsigned pack_bf16x2(__nv_bfloat16 a, __nv_bfloat16 b) {
    return (unsigned)__bfloat16_as_ushort(a) | ((unsigned)__bfloat16_as_ushort(b) << 16);
}

// ================= counters + router =================
__global__ void zero_counts_kernel() {
    if (threadIdx.x < NEXP) g_counts[threadIdx.x] = 0;
}

__global__ void gate_kernel(const float* __restrict__ x, const float* __restrict__ gw) {
    int t = blockIdx.x;
    __shared__ float xs[HDIM];
    __shared__ float logits[NEXP];
    const float* xrow = x + (size_t)t * HDIM;
    for (int i = threadIdx.x; i < HDIM; i += blockDim.x) xs[i] = xrow[i];
    __syncthreads();
    int warp = threadIdx.x >> 5, lane = threadIdx.x & 31;
    for (int e = warp; e < NEXP; e += 8) {
        const float* grow = gw + (size_t)e * HDIM;
        float s = 0.f;
        for (int h = lane; h < HDIM; h += 32) s += xs[h] * grow[h];
        #pragma unroll
        for (int o = 16; o > 0; o >>= 1) s += __shfl_xor_sync(0xffffffffu, s, o);
        if (lane == 0) logits[e] = s;
    }
    __syncthreads();
    if (threadIdx.x == 0) {
        float mx = -1e30f;
        for (int e = 0; e < NEXP; e++) mx = fmaxf(mx, logits[e]);
        float sc[NEXP]; float se = 0.f;
        for (int e = 0; e < NEXP; e++) { sc[e] = expf(logits[e] - mx); se += sc[e]; }
        float inv = 1.f / se;
        for (int e = 0; e < NEXP; e++) sc[e] *= inv;
        int idx[KSEL]; float w[KSEL]; float wsum = 0.f;
        bool used[NEXP];
        for (int e = 0; e < NEXP; e++) used[e] = false;
        for (int k = 0; k < KSEL; k++) {
            int best = 0; float bv = -1.f;
            for (int e = 0; e < NEXP; e++)
                if (!used[e] && sc[e] > bv) { bv = sc[e]; best = e; }
            used[best] = true; idx[k] = best; w[k] = bv; wsum += bv;
        }
        float iw = 1.f / wsum;
        for (int k = 0; k < KSEL; k++) {
            int e = idx[k];
            int pos = atomicAdd(&g_counts[e], 1);
            g_tokens[e * T_TOK + pos] = t;
            g_wts[e * T_TOK + pos]    = w[k] * iw;
        }
    }
}

// ================= conversions =================
__global__ void convert_x_kernel(const float* __restrict__ x) {
    int i = (blockIdx.x * blockDim.x + threadIdx.x) * 4;
    float4 v = *(const float4*)(x + i);
    __nv_bfloat16 h, l;
    split_bf16(v.x, h, l); g_xh[i+0] = h; g_xl[i+0] = l;
    split_bf16(v.y, h, l); g_xh[i+1] = h; g_xl[i+1] = l;
    split_bf16(v.z, h, l); g_xh[i+2] = h; g_xl[i+2] = l;
    split_bf16(v.w, h, l); g_xh[i+3] = h; g_xl[i+3] = l;
}

// fp32 in [R][C] (batch z) -> bf16 hi/lo out [C][R]
__global__ void transpose_split_kernel(const float* __restrict__ in, int which, int R, int C) {
    __shared__ float tile[32][33];
    __nv_bfloat16 *oh, *ol;
    switch (which) {
        case 0: oh = g_wgh; ol = g_wgl; break;
        case 1: oh = g_wuh; ol = g_wul; break;
        case 2: oh = g_wdh; ol = g_wdl; break;
        case 3: oh = g_sgh; ol = g_sgl; break;
        case 4: oh = g_suh; ol = g_sul; break;
        default: oh = g_sdh; ol = g_sdl; break;
    }
    size_t boff = (size_t)blockIdx.z * R * C;
    const float* src = in + boff;
    int c0 = blockIdx.x * 32, r0 = blockIdx.y * 32;
    int tx = threadIdx.x, ty = threadIdx.y;
    #pragma unroll
    for (int i = 0; i < 4; i++)
        tile[ty + i * 8][tx] = src[(size_t)(r0 + ty + i * 8) * C + c0 + tx];
    __syncthreads();
    #pragma unroll
    for (int i = 0; i < 4; i++) {
        float v = tile[tx][ty + i * 8];
        __nv_bfloat16 h, l; split_bf16(v, h, l);
        size_t o = boff + (size_t)(c0 + ty + i * 8) * R + r0 + tx;
        oh[o] = h; ol[o] = l;
    }
}

// ================= up GEMM: mma.sync bf16, CTA 128 x 64(int), g+u =================
__global__ __launch_bounds__(256, 1)
void up_mma_kernel(int routed) {
    __shared__ __nv_bfloat16 AsH[128 * AST], AsL[128 * AST];
    __shared__ __nv_bfloat16 BsH[128 * AST], BsL[128 * AST];   // rows 0-63 g, 64-127 u
    const int e  = blockIdx.z;
    const int n0 = blockIdx.x * 64;
    const int m0 = blockIdx.y * 128;
    const int count = routed ? g_counts[e] : T_TOK;
    if (m0 >= count) return;

    const int tid = threadIdx.x, lane = tid & 31, w = tid >> 5;
    const int wm = w & 1, wn = w >> 1;          // warp tile: M 64, N_int 16
    const int gid = lane >> 2, tig = lane & 3;

    // --- fill mapping: 2 threads per row, 2 uint4 each (32 bf16 slab) ---
    const int frow = tid >> 1, part = tid & 1;
    int am = m0 + frow;
    int tok = routed ? g_tokens[e * T_TOK + am] : am;   // stale beyond count: discarded later
    const uint4* gAH = (const uint4*)(g_xh + (size_t)tok * HDIM);
    const uint4* gAL = (const uint4*)(g_xl + (size_t)tok * HDIM);
    const int mat = frow >> 6, bn = n0 + (frow & 63);
    const uint4 *gBH, *gBL;
    if (routed) {
        size_t off = ((size_t)e * IDIM + bn) * HDIM;
        gBH = (const uint4*)((mat ? g_wuh : g_wgh) + off);
        gBL = (const uint4*)((mat ? g_wul : g_wgl) + off);
    } else {
        size_t off = (size_t)bn * HDIM;
        gBH = (const uint4*)((mat ? g_suh : g_sgh) + off);
        gBL = (const uint4*)((mat ? g_sul : g_sgl) + off);
    }

    float cg[4][2][4], cu[4][2][4];
    #pragma unroll
    for (int i = 0; i < 4; i++)
        #pragma unroll
        for (int j = 0; j < 2; j++)
            #pragma unroll
            for (int q = 0; q < 4; q++) { cg[i][j][q] = 0.f; cu[i][j][q] = 0.f; }

    int base = part * 2;
    uint4 pAh0 = gAH[base], pAh1 = gAH[base + 1];
    uint4 pAl0 = gAL[base], pAl1 = gAL[base + 1];
    uint4 pBh0 = gBH[base], pBh1 = gBH[base + 1];
    uint4 pBl0 = gBL[base], pBl1 = gBL[base + 1];

    const int S = HDIM / 32;
    for (int s = 0; s < S; s++) {
        __syncthreads();
        {
            char* d = (char*)AsH + frow * 80 + part * 32;
            *(uint4*)d = pAh0; *(uint4*)(d + 16) = pAh1;
            d = (char*)AsL + frow * 80 + part * 32;
            *(uint4*)d = pAl0; *(uint4*)(d + 16) = pAl1;
            d = (char*)BsH + frow * 80 + part * 32;
            *(uint4*)d = pBh0; *(uint4*)(d + 16) = pBh1;
            d = (char*)BsL + frow * 80 + part * 32;
            *(uint4*)d = pBl0; *(uint4*)(d + 16) = pBl1;
        }
        __syncthreads();
        if (s + 1 < S) {
            int b2 = (s + 1) * 4 + part * 2;
            pAh0 = gAH[b2]; pAh1 = gAH[b2 + 1];
            pAl0 = gAL[b2]; pAl1 = gAL[b2 + 1];
            pBh0 = gBH[b2]; pBh1 = gBH[b2 + 1];
            pBl0 = gBL[b2]; pBl1 = gBL[b2 + 1];
        }
        #pragma unroll
        for (int kk = 0; kk < 2; kk++) {
            int k2 = kk * 16 + tig * 2;
            unsigned ah[4][4], al[4][4];
            #pragma unroll
            for (int mi = 0; mi < 4; mi++) {
                int r = wm * 64 + mi * 16 + gid;
                const __nv_bfloat16* p = &AsH[r * AST + k2];
                ah[mi][0] = *(const unsigned*)p;
                ah[mi][1] = *(const unsigned*)(p + 8 * AST);
                ah[mi][2] = *(const unsigned*)(p + 8);
                ah[mi][3] = *(const unsigned*)(p + 8 * AST + 8);
                const __nv_bfloat16* q = &AsL[r * AST + k2];
                al[mi][0] = *(const unsigned*)q;
                al[mi][1] = *(const unsigned*)(q + 8 * AST);
                al[mi][2] = *(const unsigned*)(q + 8);
                al[mi][3] = *(const unsigned*)(q + 8 * AST + 8);
            }
            #pragma unroll
            for (int ni = 0; ni < 2; ni++) {
                #pragma unroll
                for (int mat2 = 0; mat2 < 2; mat2++) {
                    int nr = mat2 * 64 + wn * 16 + ni * 8 + gid;
                    const __nv_bfloat16* pb = &BsH[nr * AST + k2];
                    unsigned bh[2] = { *(const unsigned*)pb, *(const unsigned*)(pb + 8) };
                    const __nv_bfloat16* qb = &BsL[nr * AST + k2];
                    unsigned bl[2] = { *(const unsigned*)qb, *(const unsigned*)(qb + 8) };
                    #pragma unroll
                    for (int mi = 0; mi < 4; mi++) {
                        float* c = mat2 ? cu[mi][ni] : cg[mi][ni];
                        mma16816(c, ah[mi], bh);
                        mma16816(c, ah[mi], bl);
                        mma16816(c, al[mi], bh);
                    }
                }
            }
        }
    }

    // --- SwiGLU epilogue -> bf16 hi/lo activation scratch ---
    #pragma unroll
    for (int mi = 0; mi < 4; mi++) {
        #pragma unroll
        for (int ni = 0; ni < 2; ni++) {
            int c = n0 + wn * 16 + ni * 8 + tig * 2;
            #pragma unroll
            for (int half = 0; half < 2; half++) {
                int m = m0 + wm * 64 + mi * 16 + gid + half * 8;
                if (m >= count) continue;
                float wt = routed ? g_wts[e * T_TOK + m] : 1.0f;
                float g0 = cg[mi][ni][half * 2], g1 = cg[mi][ni][half * 2 + 1];
                float u0 = cu[mi][ni][half * 2], u1 = cu[mi][ni][half * 2 + 1];
                float a0 = (g0 / (1.f + expf(-g0))) * u0 * wt;
                float a1 = (g1 / (1.f + expf(-g1))) * u1 * wt;
                __nv_bfloat16 h0, l0, h1, l1;
                split_bf16(a0, h0, l0); split_bf16(a1, h1, l1);
                size_t ro = routed ? ((size_t)e * T_TOK + m) * IDIM : (size_t)m * ISDIM;
                *(unsigned*)( (routed ? g_ah : g_sah) + ro + c ) = pack_bf16x2(h0, h1);
                *(unsigned*)( (routed ? g_al : g_sal) + ro + c ) = pack_bf16x2(l0, l1);
            }
        }
    }
}

// ================= down GEMM: mma.sync bf16, CTA 128 x 128 =================
__global__ __launch_bounds__(256, 1)
void down_mma_kernel(float* __restrict__ out, int routed) {
    __shared__ __nv_bfloat16 AsH[128 * AST], AsL[128 * AST];
    __shared__ __nv_bfloat16 BsH[128 * AST], BsL[128 * AST];
    const int e  = blockIdx.z;
    const int n0 = blockIdx.x * 128;
    const int m0 = blockIdx.y * 128;
    const int count = routed ? g_counts[e] : T_TOK;
    if (m0 >= count) return;
    const int Kd = routed ? IDIM : ISDIM;

    const int tid = threadIdx.x, lane = tid & 31, w = tid >> 5;
    const int wm = w & 1, wn = w >> 1;          // warp tile 64 x 32
    const int gid = lane >> 2, tig = lane & 3;

    const int frow = tid >> 1, part = tid & 1;
    const uint4 *gAH, *gAL;
    if (routed) {
        size_t ro = ((size_t)e * T_TOK + m0 + frow) * IDIM;
        gAH = (const uint4*)(g_ah + ro); gAL = (const uint4*)(g_al + ro);
    } else {
        size_t ro = (size_t)(m0 + frow) * ISDIM;
        gAH = (const uint4*)(g_sah + ro); gAL = (const uint4*)(g_sal + ro);
    }
    const uint4 *gBH, *gBL;
    {
        int h = n0 + frow;
        if (routed) {
            size_t off = ((size_t)e * HDIM + h) * IDIM;
            gBH = (const uint4*)(g_wdh + off); gBL = (const uint4*)(g_wdl + off);
        } else {
            size_t off = (size_t)h * ISDIM;
            gBH = (const uint4*)(g_sdh + off); gBL = (const uint4*)(g_sdl + off);
        }
    }

    float cc[4][4][4];
    #pragma unroll
    for (int i = 0; i < 4; i++)
        #pragma unroll
        for (int j = 0; j < 4; j++)
            #pragma unroll
            for (int q = 0; q < 4; q++) cc[i][j][q] = 0.f;

    int base = part * 2;
    uint4 pAh0 = gAH[base], pAh1 = gAH[base + 1];
    uint4 pAl0 = gAL[base], pAl1 = gAL[base + 1];
    uint4 pBh0 = gBH[base], pBh1 = gBH[base + 1];
    uint4 pBl0 = gBL[base], pBl1 = gBL[base + 1];

    const int S = Kd / 32;
    for (int s = 0; s < S; s++) {
        __syncthreads();
        {
            char* d = (char*)AsH + frow * 80 + part * 32;
            *(uint4*)d = pAh0; *(uint4*)(d + 16) = pAh1;
            d = (char*)AsL + frow * 80 + part * 32;
            *(uint4*)d = pAl0; *(uint4*)(d + 16) = pAl1;
            d = (char*)BsH + frow * 80 + part * 32;
            *(uint4*)d = pBh0; *(uint4*)(d + 16) = pBh1;
            d = (char*)BsL + frow * 80 + part * 32;
            *(uint4*)d = pBl0; *(uint4*)(d + 16) = pBl1;
        }
        __syncthreads();
        if (s + 1 < S) {
            int b2 = (s + 1) * 4 + part * 2;
            pAh0 = gAH[b2]; pAh1 = gAH[b2 + 1];
            pAl0 = gAL[b2]; pAl1 = gAL[b2 + 1];
            pBh0 = gBH[b2]; pBh1 = gBH[b2 + 1];
            pBl0 = gBL[b2]; pBl1 = gBL[b2 + 1];
        }
        #pragma unroll
        for (int kk = 0; kk < 2; kk++) {
            int k2 = kk * 16 + tig * 2;
            unsigned ah[4][4], al[4][4];
            #pragma unroll
            for (int mi = 0; mi < 4; mi++) {
                int r = wm * 64 + mi * 16 + gid;
                const __nv_bfloat16* p = &AsH[r * AST + k2];
                ah[mi][0] = *(const unsigned*)p;
                ah[mi][1] = *(const unsigned*)(p + 8 * AST);
                ah[mi][2] = *(const unsigned*)(p + 8);
                ah[mi][3] = *(const unsigned*)(p + 8 * AST + 8);
                const __nv_bfloat16* q = &AsL[r * AST + k2];
                al[mi][0] = *(const unsigned*)q;
                al[mi][1] = *(const unsigned*)(q + 8 * AST);
                al[mi][2] = *(const unsigned*)(q + 8);
                al[mi][3] = *(const unsigned*)(q + 8 * AST + 8);
            }
            #pragma unroll
            for (int ni = 0; ni < 4; ni++) {
                int nr = wn * 32 + ni * 8 + gid;
                const __nv_bfloat16* pb = &BsH[nr * AST + k2];
                unsigned bh[2] = { *(const unsigned*)pb, *(const unsigned*)(pb + 8) };
                const __nv_bfloat16* qb = &BsL[nr * AST + k2];
                unsigned bl[2] = { *(const unsigned*)qb, *(const unsigned*)(qb + 8) };
                #pragma unroll
                for (int mi = 0; mi < 4; mi++) {
                    mma16816(cc[mi][ni], ah[mi], bh);
                    mma16816(cc[mi][ni], ah[mi], bl);
                    mma16816(cc[mi][ni], al[mi], bh);
                }
            }
        }
    }

    #pragma unroll
    for (int mi = 0; mi < 4; mi++) {
        #pragma unroll
        for (int ni = 0; ni < 4; ni++) {
            int h = n0 + wn * 32 + ni * 8 + tig * 2;
            #pragma unroll
            for (int half = 0; half < 2; half++) {
                int m = m0 + wm * 64 + mi * 16 + gid + half * 8;
                if (m >= count) continue;
                float v0 = cc[mi][ni][half * 2], v1 = cc[mi][ni][half * 2 + 1];
                if (routed) {
                    int t = g_tokens[e * T_TOK + m];
                    atomicAdd(out + (size_t)t * HDIM + h,     v0);
                    atomicAdd(out + (size_t)t * HDIM + h + 1, v1);
                } else {
                    float2 v = make_float2(v0, v1);
                    *(float2*)(out + (size_t)m * HDIM + h) = v;
                }
            }
        }
    }
}

// ================= launch =================
extern "C" void kernel_launch(void* const* d_in, const int* in_sizes, int n_in,
                              void* d_out, int out_size) {
    (void)in_sizes; (void)n_in; (void)out_size;
    const float* x       = (const float*)d_in[0];
    const float* gate_w  = (const float*)d_in[1];
    const float* w_gate  = (const float*)d_in[2];
    const float* w_up    = (const float*)d_in[3];
    const float* w_down  = (const float*)d_in[4];
    const float* sw_gate = (const float*)d_in[5];
    const float* sw_up   = (const float*)d_in[6];
    const float* sw_down = (const float*)d_in[7];
    float* out = (float*)d_out;

    zero_counts_kernel<<<1, 32>>>();
    gate_kernel<<<T_TOK, 256>>>(x, gate_w);
    convert_x_kernel<<<(T_TOK * HDIM) / 1024, 256>>>(x);

    dim3 blk(32, 8);
    transpose_split_kernel<<<dim3(IDIM/32,  HDIM/32, NEXP), blk>>>(w_gate,  0, HDIM,  IDIM);
    transpose_split_kernel<<<dim3(IDIM/32,  HDIM/32, NEXP), blk>>>(w_up,    1, HDIM,  IDIM);
    transpose_split_kernel<<<dim3(HDIM/32,  IDIM/32, NEXP), blk>>>(w_down,  2, IDIM,  HDIM);
    transpose_split_kernel<<<dim3(ISDIM/32, HDIM/32, 1),    blk>>>(sw_gate, 3, HDIM,  ISDIM);
    transpose_split_kernel<<<dim3(ISDIM/32, HDIM/32, 1),    blk>>>(sw_up,   4, HDIM,  ISDIM);
    transpose_split_kernel<<<dim3(HDIM/32,  ISDIM/32, 1),   blk>>>(sw_down, 5, ISDIM, HDIM);

    // routed + shared gate/up (SwiGLU fused)
    up_mma_kernel<<<dim3(IDIM / 64,  T_TOK / 128, NEXP), 256>>>(1);
    up_mma_kernel<<<dim3(ISDIM / 64, T_TOK / 128, 1),    256>>>(0);

    // shared down first (plain stores fully initialize out), then routed atomics
    down_mma_kernel<<<dim3(HDIM / 128, T_TOK / 128, 1),    256>>>(out, 0);
    down_mma_kernel<<<dim3(HDIM / 128, T_TOK / 128, NEXP), 256>>>(out, 1);
}